// round 1
// baseline (speedup 1.0000x reference)
#include <cuda_runtime.h>
#include <math.h>

// Problem constants (ScaledDotProduct_49314814493101):
//   B=4, S=8, C=1024, DK=1024, 3DK=3072, MAX_LEN=8192 (derived), size = out_size/(B*DK)
#define BB 4
#define CC 1024
#define DK 1024
#define TDK 3072
#define NSEG 8
#define CSEG (CC / NSEG)      // 128
#define CHUNK 128
#define MAXCH 64              // 8192/128
#define MAXLEN_PAD 8192

// -------- scratch (device globals; no allocation allowed) --------
__device__ float g_qkv_part[NSEG * BB * TDK];   // projection partials
__device__ float g_qkv[BB * TDK];               // q | k_new | v_new per batch
__device__ float g_w[BB * MAXLEN_PAD];          // raw logits
__device__ float g_e[BB * MAXLEN_PAD];          // exp(w - M)
__device__ float g_invD[BB * MAXLEN_PAD];       // 1 / prefix-sum(e)
__device__ float g_P[BB * MAXCH * DK];          // chunk partial vector sums

// ---------------- K1: QKV projection, partial over c-segments ----------------
// grid (24, 8), block 128. Block (jt, seg): j = jt*128+tid, c in [seg*128, seg*128+128)
__global__ void k_proj_partial(const float* __restrict__ x,
                               const float* __restrict__ W, int S) {
    int jt  = blockIdx.x;
    int seg = blockIdx.y;
    int j   = jt * 128 + threadIdx.x;
    int c0  = seg * CSEG;

    __shared__ float xs[BB][CSEG];
    for (int i = threadIdx.x; i < BB * CSEG; i += 128) {
        int b = i / CSEG, cc = i % CSEG;
        xs[b][cc] = x[(size_t)b * S * CC + (size_t)(S - 1) * CC + c0 + cc];
    }
    __syncthreads();

    float a0 = 0.f, a1 = 0.f, a2 = 0.f, a3 = 0.f;
    const float* Wp = W + (size_t)c0 * TDK + j;
#pragma unroll 8
    for (int cc = 0; cc < CSEG; cc++) {
        float w = Wp[(size_t)cc * TDK];
        a0 += xs[0][cc] * w;
        a1 += xs[1][cc] * w;
        a2 += xs[2][cc] * w;
        a3 += xs[3][cc] * w;
    }
    g_qkv_part[(size_t)(seg * BB + 0) * TDK + j] = a0;
    g_qkv_part[(size_t)(seg * BB + 1) * TDK + j] = a1;
    g_qkv_part[(size_t)(seg * BB + 2) * TDK + j] = a2;
    g_qkv_part[(size_t)(seg * BB + 3) * TDK + j] = a3;
}

// ---------------- K1b: reduce partials + bias ----------------
__global__ void k_proj_reduce(const float* __restrict__ bias) {
    int idx = blockIdx.x * 256 + threadIdx.x;   // over BB*TDK = 12288
    if (idx >= BB * TDK) return;
    int b = idx / TDK, j = idx % TDK;
    float s = bias[j];
#pragma unroll
    for (int seg = 0; seg < NSEG; seg++)
        s += g_qkv_part[(size_t)(seg * BB + b) * TDK + j];
    g_qkv[(size_t)b * TDK + j] = s;
}

// ---------------- K2: logits w[b,T] = q . k_T / sqrt(DK) ----------------
// block 256 (8 warps, one T each); grid ((size+7)/8, B)
__global__ void k_logits(const float* __restrict__ kc, int ML, int size, int tok) {
    int b    = blockIdx.y;
    int warp = threadIdx.x >> 5;
    int lane = threadIdx.x & 31;
    int T    = blockIdx.x * 8 + warp;

    __shared__ float qs[DK];
    for (int i = threadIdx.x; i < DK; i += 256)
        qs[i] = g_qkv[(size_t)b * TDK + i];
    __syncthreads();

    if (T >= size) return;
    const float* krow = (T == tok) ? (g_qkv + (size_t)b * TDK + DK)
                                   : (kc + ((size_t)b * ML + T) * DK);
    float acc = 0.f;
#pragma unroll
    for (int i = 0; i < 8; i++) {
        float4 kv = *(const float4*)(krow + i * 128 + lane * 4);
        float4 qv = *(const float4*)(qs + i * 128 + lane * 4);
        acc += kv.x * qv.x + kv.y * qv.y + kv.z * qv.z + kv.w * qv.w;
    }
#pragma unroll
    for (int o = 16; o; o >>= 1) acc += __shfl_xor_sync(0xFFFFFFFFu, acc, o);
    if (lane == 0) g_w[(size_t)b * MAXLEN_PAD + T] = acc * 0.03125f;  // 1/sqrt(1024)
}

// ---------------- K3: per-batch max, exp, prefix-sum denominators ----------------
// grid B, block 256
__global__ void k_softmax_scan(int size) {
    int b   = blockIdx.x;
    int tid = threadIdx.x;
    const float* wrow = g_w + (size_t)b * MAXLEN_PAD;
    float* erow = g_e + (size_t)b * MAXLEN_PAD;
    float* drow = g_invD + (size_t)b * MAXLEN_PAD;

    int CH = (size + 255) / 256;
    int lo = tid * CH;
    int hi = min(lo + CH, size);

    // 1) global max
    float m = -3.4e38f;
    for (int t = lo; t < hi; t++) m = fmaxf(m, wrow[t]);
    __shared__ float red[256];
    red[tid] = m;
    __syncthreads();
    for (int s = 128; s; s >>= 1) {
        if (tid < s) red[tid] = fmaxf(red[tid], red[tid + s]);
        __syncthreads();
    }
    float M = red[0];
    __syncthreads();

    // 2) exp + per-thread local sum
    float ls = 0.f;
    for (int t = lo; t < hi; t++) {
        float e = expf(wrow[t] - M);
        erow[t] = e;
        ls += e;
    }
    red[tid] = ls;
    __syncthreads();

    // 3) inclusive Hillis-Steele scan over thread sums
    for (int off = 1; off < 256; off <<= 1) {
        float v = (tid >= off) ? red[tid - off] : 0.f;
        __syncthreads();
        red[tid] += v;
        __syncthreads();
    }
    float run = (tid > 0) ? red[tid - 1] : 0.f;   // exclusive base

    // 4) running inverse denominators
    for (int t = lo; t < hi; t++) {
        run += erow[t];
        drow[t] = 1.0f / run;
    }
}

// ---------------- K4a: chunk partial vector sums ----------------
// grid (DK/256, nch, B), block 256
__global__ void k_chunk_sums(const float* __restrict__ vc, int ML, int size, int tok) {
    int b  = blockIdx.z;
    int ch = blockIdx.y;
    int c  = blockIdx.x * 256 + threadIdx.x;
    int t0 = ch * CHUNK;
    int t1 = min(t0 + CHUNK, size);

    __shared__ float es[CHUNK];
    if (threadIdx.x < CHUNK) {
        int t = t0 + threadIdx.x;
        es[threadIdx.x] = (t < size) ? g_e[(size_t)b * MAXLEN_PAD + t] : 0.f;
    }
    __syncthreads();

    const float* vb = vc + (size_t)b * ML * DK;
    float vnew = g_qkv[(size_t)b * TDK + 2 * DK + c];
    float acc = 0.f;
#pragma unroll 4
    for (int t = t0; t < t1; t++) {
        float v = (t == tok) ? vnew : vb[(size_t)t * DK + c];
        acc += es[t - t0] * v;
    }
    g_P[((size_t)b * MAXCH + ch) * DK + c] = acc;
}

// ---------------- K4b: exclusive prefix over chunks (in place) ----------------
// grid 16, block 256 -> one thread per (b,c)
__global__ void k_chunk_prefix(int nch) {
    int idx = blockIdx.x * 256 + threadIdx.x;   // BB*DK = 4096
    if (idx >= BB * DK) return;
    int b = idx / DK, c = idx % DK;
    float run = 0.f;
    for (int ch = 0; ch < nch; ch++) {
        size_t p = ((size_t)b * MAXCH + ch) * DK + c;
        float v = g_P[p];
        g_P[p] = run;
        run += v;
    }
}

// ---------------- K4c: final pass, write outputs ----------------
// grid (DK/256, nch, B), block 256
__global__ void k_output(const float* __restrict__ vc, float* __restrict__ out,
                         int ML, int size, int tok) {
    int b  = blockIdx.z;
    int ch = blockIdx.y;
    int c  = blockIdx.x * 256 + threadIdx.x;
    int t0 = ch * CHUNK;
    int t1 = min(t0 + CHUNK, size);

    __shared__ float es[CHUNK];
    __shared__ float ds[CHUNK];
    if (threadIdx.x < CHUNK) {
        int t = t0 + threadIdx.x;
        es[threadIdx.x] = (t < size) ? g_e[(size_t)b * MAXLEN_PAD + t] : 0.f;
        ds[threadIdx.x] = (t < size) ? g_invD[(size_t)b * MAXLEN_PAD + t] : 1.f;
    }
    __syncthreads();

    const float* vb = vc + (size_t)b * ML * DK;
    float vnew = g_qkv[(size_t)b * TDK + 2 * DK + c];
    float acc = g_P[((size_t)b * MAXCH + ch) * DK + c];
#pragma unroll 4
    for (int t = t0; t < t1; t++) {
        float v = (t == tok) ? vnew : vb[(size_t)t * DK + c];
        acc += es[t - t0] * v;
        out[((size_t)b * size + t) * DK + c] = acc * ds[t - t0];
    }
}

// ---------------- launch ----------------
extern "C" void kernel_launch(void* const* d_in, const int* in_sizes, int n_in,
                              void* d_out, int out_size) {
    const float* x    = (const float*)d_in[0];   // (B,S,C)
    const float* W    = (const float*)d_in[1];   // (C, 3DK)
    const float* bias = (const float*)d_in[2];   // (3DK,)
    const float* kc   = (const float*)d_in[3];   // (B, ML, DK)
    const float* vc   = (const float*)d_in[4];   // (B, ML, DK)
    // d_in[5] = token_ind (device scalar) -- derived on host instead:
    int S    = in_sizes[0] / (BB * CC);          // 8
    int ML   = in_sizes[3] / (BB * DK);          // 8192
    int size = out_size / (BB * DK);             // token_ind + 1 (4096)
    int tok  = size - 1;
    int nch  = (size + CHUNK - 1) / CHUNK;

    k_proj_partial<<<dim3(TDK / 128, NSEG), 128>>>(x, W, S);
    k_proj_reduce<<<(BB * TDK + 255) / 256, 256>>>(bias);
    k_logits<<<dim3((size + 7) / 8, BB), 256>>>(kc, ML, size, tok);
    k_softmax_scan<<<BB, 256>>>(size);
    k_chunk_sums<<<dim3(DK / 256, nch, BB), 256>>>(vc, ML, size, tok);
    k_chunk_prefix<<<(BB * DK + 255) / 256, 256>>>(nch);
    k_output<<<dim3(DK / 256, nch, BB), 256>>>(vc, (float*)d_out, ML, size, tok);
}